// round 1
// baseline (speedup 1.0000x reference)
#include <cuda_runtime.h>
#include <cuda_bf16.h>
#include <cstdint>

// Problem constants
#define T_LEN 512
#define BATCH 32
#define DIM   512   // D == H
#define G4    2048  // 4*H
#define NCTA_DIR 64 // recurrence CTAs per direction (8 H-cols each)

// Scratch: x_pre stored as [dir][t][g (0..2047)][b]  (b fastest -> coalesced reads in recurrence)
__device__ float g_xpre[(size_t)2 * T_LEN * G4 * BATCH]; // 67,108,864 floats = 256 MB
__device__ int   g_sync[2 * T_LEN];                      // per-(dir,step) arrival counters

// ---------------------------------------------------------------------------
// init: zero sync counters (device globals persist across graph replays)
// ---------------------------------------------------------------------------
__global__ void init_sync_kernel() {
    int i = blockIdx.x * blockDim.x + threadIdx.x;
    if (i < 2 * T_LEN) g_sync[i] = 0;
}

// ---------------------------------------------------------------------------
// Phase 1: C[g][m] = sum_k W_ih[g][k] * x[m][k] + (b_ih[g]+b_hh[g])
//   W_ih viewed as [4096][512], x as [16384][512] (both K-major).
//   Stored transposed into g_xpre[d][t][g'][b].
//   128x128 CTA tile, K-tile 8, 256 threads, 8x8 microtile.
// ---------------------------------------------------------------------------
__global__ __launch_bounds__(256, 2)
void xpre_gemm_kernel(const float* __restrict__ W,
                      const float* __restrict__ x,
                      const float* __restrict__ bih,
                      const float* __restrict__ bhh)
{
    __shared__ float As[8][128];  // As[k][g]
    __shared__ float Bs[8][128];  // Bs[k][m]

    const int g0 = blockIdx.x * 128;
    const int m0 = blockIdx.y * 128;
    const int tid = threadIdx.x;

    const int lrow = tid >> 1;
    const int lseg = (tid & 1) * 4;
    const float* Ap = W + (size_t)(g0 + lrow) * DIM + lseg;
    const float* Bp = x + (size_t)(m0 + lrow) * DIM + lseg;

    const int tx = tid & 15;
    const int ty = tid >> 4;

    float acc[8][8];
#pragma unroll
    for (int i = 0; i < 8; i++)
#pragma unroll
        for (int j = 0; j < 8; j++) acc[i][j] = 0.f;

    float4 apre = *(const float4*)Ap;
    float4 bpre = *(const float4*)Bp;

    for (int k0 = 0; k0 < DIM; k0 += 8) {
        As[lseg + 0][lrow] = apre.x; As[lseg + 1][lrow] = apre.y;
        As[lseg + 2][lrow] = apre.z; As[lseg + 3][lrow] = apre.w;
        Bs[lseg + 0][lrow] = bpre.x; Bs[lseg + 1][lrow] = bpre.y;
        Bs[lseg + 2][lrow] = bpre.z; Bs[lseg + 3][lrow] = bpre.w;
        __syncthreads();

        if (k0 + 8 < DIM) {
            apre = *(const float4*)(Ap + k0 + 8);
            bpre = *(const float4*)(Bp + k0 + 8);
        }

#pragma unroll
        for (int k = 0; k < 8; k++) {
            float a[8], b[8];
            *(float4*)(a)     = *(const float4*)&As[k][ty * 4];
            *(float4*)(a + 4) = *(const float4*)&As[k][64 + ty * 4];
            *(float4*)(b)     = *(const float4*)&Bs[k][tx * 4];
            *(float4*)(b + 4) = *(const float4*)&Bs[k][64 + tx * 4];
#pragma unroll
            for (int i = 0; i < 8; i++)
#pragma unroll
                for (int j = 0; j < 8; j++)
                    acc[i][j] += a[i] * b[j];
        }
        __syncthreads();
    }

    // store transposed with fused bias
#pragma unroll
    for (int i = 0; i < 8; i++) {
        int g = g0 + ((i < 4) ? (ty * 4 + i) : (64 + ty * 4 + (i - 4)));
        int d  = g >> 11;
        int gp = g & 2047;
        float bias = bih[g] + bhh[g];
        size_t base = (size_t)d * ((size_t)T_LEN * G4 * BATCH) + (size_t)gp * BATCH;
#pragma unroll
        for (int j = 0; j < 8; j++) {
            int m = m0 + ((j < 4) ? (tx * 4 + j) : (64 + tx * 4 + (j - 4)));
            int t  = m >> 5;
            int bb = m & 31;
            g_xpre[base + (size_t)t * (G4 * BATCH) + bb] = acc[i][j] + bias;
        }
    }
}

// ---------------------------------------------------------------------------
// Phase 2: persistent recurrence kernel. 128 CTAs (1/SM, all co-resident).
//   CTA -> (dir, 8 H-columns). W_hh slice (32 rows x 512) resident in SMEM.
//   Per step: flag-wait -> load h_prev (L2 broadcast) -> GEMM slice ->
//   gate exchange via SMEM -> LSTM update -> write h into output -> signal.
//   Output tensor itself is the h history (no extra h buffer).
// ---------------------------------------------------------------------------
#define HPAD 516  // row pad: 516 % 32 == 4 -> conflict-free strided LDS.128

__global__ void lstm_rec_kernel(const float* __restrict__ h0,
                                const float* __restrict__ c0,
                                const float* __restrict__ Whh,
                                float* __restrict__ out,    // [T][B][1024]
                                float* __restrict__ hout,   // [2][B][512]
                                float* __restrict__ cout)   // [2][B][512]
{
    extern __shared__ float sm[];
    float* Wsh  = sm;                    // [32][HPAD]
    float* hsh  = Wsh + 32 * HPAD;       // [32][HPAD]
    float* gbuf = hsh + 32 * HPAD;       // [32][33]
    float* csl  = gbuf + 32 * 33;        // [8][32]

    const int cta  = blockIdx.x;
    const int dir  = cta >> 6;
    const int j0   = (cta & (NCTA_DIR - 1)) * 8;
    const int tid  = threadIdx.x;
    const int warp = tid >> 5;
    const int lane = tid & 31;

    // Load W_hh slice: local row lr = q*8+cc  ->  global row q*512 + j0 + cc
    {
        int lr = tid >> 3, part = tid & 7;
        int q = lr >> 3, cc = lr & 7;
        const float* src = Whh + ((size_t)dir * G4 + q * DIM + j0 + cc) * DIM + part * 64;
        float* dst = Wsh + lr * HPAD + part * 64;
#pragma unroll
        for (int i = 0; i < 64; i += 4)
            *(float4*)(dst + i) = *(const float4*)(src + i);
    }
    // c state slice
    {
        int cc = tid >> 5, b = tid & 31;
        csl[cc * 32 + b] = c0[((size_t)dir * BATCH + b) * DIM + j0 + cc];
    }
    __syncthreads();

    const float* w0 = Wsh + (warp * 4 + 0) * HPAD;
    const float* w1 = Wsh + (warp * 4 + 1) * HPAD;
    const float* w2 = Wsh + (warp * 4 + 2) * HPAD;
    const float* w3 = Wsh + (warp * 4 + 3) * HPAD;
    const float* hrow = hsh + lane * HPAD;

    for (int s = 0; s < T_LEN; s++) {
        const int t = dir ? (T_LEN - 1 - s) : s;

        const float* hsrc;
        int hstride;
        if (s == 0) {
            hsrc = h0 + (size_t)dir * BATCH * DIM;  // [b][k], stride 512
            hstride = DIM;
        } else {
            int tp = dir ? (t + 1) : (t - 1);
            hsrc = out + (size_t)tp * (BATCH * 1024) + dir * DIM;  // per-b stride 1024
            hstride = 1024;
            if (tid == 0) {
                volatile int* f = &g_sync[dir * T_LEN + (s - 1)];
                while (*f < NCTA_DIR) { __nanosleep(64); }
            }
            __syncthreads();
            __threadfence();
        }

        // load h_prev [32][512] -> hsh (coalesced float4)
#pragma unroll
        for (int it = 0; it < 16; it++) {
            int f  = tid + it * 256;
            int b  = f >> 7;
            int c4 = (f & 127) * 4;
            *(float4*)(hsh + b * HPAD + c4) =
                *(const float4*)(hsrc + (size_t)b * hstride + c4);
        }
        __syncthreads();

        // gates slice: warp -> 4 local rows, lane -> batch
        float a0 = 0.f, a1 = 0.f, a2 = 0.f, a3 = 0.f;
#pragma unroll 8
        for (int k4 = 0; k4 < DIM / 4; k4++) {
            float4 hv = *(const float4*)(hrow + k4 * 4);
            float4 wv;
            wv = *(const float4*)(w0 + k4 * 4);
            a0 += wv.x * hv.x + wv.y * hv.y + wv.z * hv.z + wv.w * hv.w;
            wv = *(const float4*)(w1 + k4 * 4);
            a1 += wv.x * hv.x + wv.y * hv.y + wv.z * hv.z + wv.w * hv.w;
            wv = *(const float4*)(w2 + k4 * 4);
            a2 += wv.x * hv.x + wv.y * hv.y + wv.z * hv.z + wv.w * hv.w;
            wv = *(const float4*)(w3 + k4 * 4);
            a3 += wv.x * hv.x + wv.y * hv.y + wv.z * hv.z + wv.w * hv.w;
        }

        // add x_pre (bias already folded) and stage gates in SMEM
        {
            const float* xp = g_xpre + (size_t)dir * ((size_t)T_LEN * G4 * BATCH)
                                     + (size_t)t * (G4 * BATCH);
            float av[4] = {a0, a1, a2, a3};
#pragma unroll
            for (int r = 0; r < 4; r++) {
                int lr = warp * 4 + r;
                int g  = (lr >> 3) * DIM + j0 + (lr & 7);
                gbuf[lr * 33 + lane] = av[r] + xp[(size_t)g * BATCH + lane];
            }
        }
        __syncthreads();

        // LSTM elementwise update: thread -> (cc, b)
        {
            int cc = tid >> 5, b = tid & 31;
            float xi = gbuf[(0  + cc) * 33 + b];
            float xf = gbuf[(8  + cc) * 33 + b];
            float xg = gbuf[(16 + cc) * 33 + b];
            float xo = gbuf[(24 + cc) * 33 + b];
            float ig = 1.f / (1.f + __expf(-xi));
            float fg = 1.f / (1.f + __expf(-xf));
            float gg = tanhf(xg);
            float og = 1.f / (1.f + __expf(-xo));
            float c  = fg * csl[cc * 32 + b] + ig * gg;
            csl[cc * 32 + b] = c;
            float h  = og * tanhf(c);
            out[(size_t)t * (BATCH * 1024) + (size_t)b * 1024 + dir * DIM + j0 + cc] = h;
            if (s == T_LEN - 1) {
                hout[((size_t)dir * BATCH + b) * DIM + j0 + cc] = h;
                cout[((size_t)dir * BATCH + b) * DIM + j0 + cc] = c;
            }
        }

        __threadfence();
        __syncthreads();
        if (tid == 0) atomicAdd(&g_sync[dir * T_LEN + s], 1);
    }
}

// ---------------------------------------------------------------------------
// launch
// ---------------------------------------------------------------------------
extern "C" void kernel_launch(void* const* d_in, const int* in_sizes, int n_in,
                              void* d_out, int out_size)
{
    (void)in_sizes; (void)n_in; (void)out_size;
    const float* x   = (const float*)d_in[0];  // [512,32,512]
    const float* h0  = (const float*)d_in[1];  // [2,32,512]
    const float* c0  = (const float*)d_in[2];  // [2,32,512]
    const float* Wih = (const float*)d_in[3];  // [2,2048,512] -> [4096,512]
    const float* bih = (const float*)d_in[4];  // [2,2048] -> [4096]
    const float* Whh = (const float*)d_in[5];  // [2,2048,512]
    const float* bhh = (const float*)d_in[6];  // [2,2048] -> [4096]

    float* out  = (float*)d_out;                         // [512,32,1024]
    float* hout = out + (size_t)T_LEN * BATCH * 1024;    // [2,32,512]
    float* cout = hout + (size_t)2 * BATCH * DIM;        // [2,32,512]

    init_sync_kernel<<<4, 256>>>();

    dim3 grid_gemm(4096 / 128, 16384 / 128);  // (g tiles, m tiles)
    xpre_gemm_kernel<<<grid_gemm, 256>>>(Wih, x, bih, bhh);

    size_t smem = (size_t)(2 * 32 * HPAD + 32 * 33 + 8 * 32) * sizeof(float);
    cudaFuncSetAttribute(lstm_rec_kernel,
                         cudaFuncAttributeMaxDynamicSharedMemorySize, (int)smem);
    lstm_rec_kernel<<<2 * NCTA_DIR, 256, smem>>>(h0, c0, Whh, out, hout, cout);
}

// round 3
// speedup vs baseline: 1.0556x; 1.0556x over previous
#include <cuda_runtime.h>
#include <cuda_bf16.h>
#include <cstdint>

// Problem constants
#define T_LEN 512
#define BATCH 32
#define DIM   512   // D == H
#define G4    2048  // 4*H
#define NCTA_DIR 64 // recurrence CTAs per direction (8 H-cols each)

// Scratch: x_pre stored as [dir][t][g (0..2047)][b]  (b fastest -> coalesced in recurrence)
__device__ float g_xpre[(size_t)2 * T_LEN * G4 * BATCH]; // 256 MB
__device__ int   g_sync[2 * T_LEN];

// bf16 hi/lo split scratch
__device__ __nv_bfloat16 g_xhi[(size_t)16384 * 512];
__device__ __nv_bfloat16 g_xlo[(size_t)16384 * 512];
__device__ __nv_bfloat16 g_whi[(size_t)4096 * 512];
__device__ __nv_bfloat16 g_wlo[(size_t)4096 * 512];

__device__ __forceinline__ uint32_t smem_to_u32(const void* p) {
    uint32_t a;
    asm("{ .reg .u64 t; cvta.to.shared.u64 t, %1; cvt.u32.u64 %0, t; }" : "=r"(a) : "l"(p));
    return a;
}

#define CP_ASYNC16(dst, src) \
    asm volatile("cp.async.cg.shared.global [%0], [%1], 16;" :: "r"(dst), "l"(src) : "memory")
#define CP_COMMIT() asm volatile("cp.async.commit_group;" ::: "memory")
#define CP_WAIT1()  asm volatile("cp.async.wait_group 1;" ::: "memory")

#define LDMATRIX_X4(r0, r1, r2, r3, addr) \
    asm volatile("ldmatrix.sync.aligned.m8n8.x4.shared.b16 {%0,%1,%2,%3}, [%4];" \
        : "=r"(r0), "=r"(r1), "=r"(r2), "=r"(r3) : "r"(addr))

#define MMA_BF16(d, a, b) \
    asm volatile("mma.sync.aligned.m16n8k16.row.col.f32.bf16.bf16.f32 " \
        "{%0,%1,%2,%3}, {%4,%5,%6,%7}, {%8,%9}, {%0,%1,%2,%3};" \
        : "+f"((d)[0]), "+f"((d)[1]), "+f"((d)[2]), "+f"((d)[3]) \
        : "r"((a)[0]), "r"((a)[1]), "r"((a)[2]), "r"((a)[3]), "r"((b)[0]), "r"((b)[1]))

// ---------------------------------------------------------------------------
__global__ void init_sync_kernel() {
    int i = blockIdx.x * blockDim.x + threadIdx.x;
    if (i < 2 * T_LEN) g_sync[i] = 0;
}

// fp32 -> bf16 hi/lo split
__global__ void split_kernel(const float* __restrict__ src,
                             __nv_bfloat16* __restrict__ hi,
                             __nv_bfloat16* __restrict__ lo, int n) {
    int i = (blockIdx.x * blockDim.x + threadIdx.x) * 4;
    if (i >= n) return;
    float4 v = *(const float4*)(src + i);
    float vs[4] = {v.x, v.y, v.z, v.w};
#pragma unroll
    for (int j = 0; j < 4; j++) {
        __nv_bfloat16 h = __float2bfloat16_rn(vs[j]);
        hi[i + j] = h;
        lo[i + j] = __float2bfloat16_rn(vs[j] - __bfloat162float(h));
    }
}

// ---------------------------------------------------------------------------
// Phase 1 (HMMA mma.sync): C[g][m] = sum_k W[g][k]*x[m][k], split-bf16, 3 passes.
//   CTA tile 128g x 128m, K in 8 chunks of 64, cp.async double-buffered.
//   8 warps: wg = wid>>1 (g quadrant of 32), wm = wid&1 (m half of 64).
//   Row pad: 72 bf16 (144B) -> conflict-free ldmatrix.
//   Epilogue: +bias[g], store transposed into g_xpre[d][t][g'][b].
// ---------------------------------------------------------------------------
#define KC 64
#define RPAD 72                       // bf16 elements per padded row
#define ARR_BYTES (128 * RPAD * 2)    // 18432
#define STAGE_BYTES (4 * ARR_BYTES)   // 73728

__global__ __launch_bounds__(256, 1)
void xpre_mma_kernel(const float* __restrict__ bih, const float* __restrict__ bhh)
{
    extern __shared__ char smem[];
    const uint32_t sb = smem_to_u32(smem);

    const int tid  = threadIdx.x;
    const int wid  = tid >> 5;
    const int lane = tid & 31;
    const int g0   = blockIdx.x * 128;
    const int m0   = blockIdx.y * 128;
    const int wg   = wid >> 1;   // 0..3
    const int wm   = wid & 1;    // 0..1

    const int grp = lane >> 2;   // groupID
    const int tig = lane & 3;

    // cp.async assignment: row = tid>>1, 4 segs of 16B per array
    const int lrow = tid >> 1;
    const int lseg = (tid & 1) * 4;
    const __nv_bfloat16* gsrc[4] = {
        g_whi + (size_t)(g0 + lrow) * 512,
        g_wlo + (size_t)(g0 + lrow) * 512,
        g_xhi + (size_t)(m0 + lrow) * 512,
        g_xlo + (size_t)(m0 + lrow) * 512
    };

    auto issue_chunk = [&](int kc) {
        const int st = kc & 1;
        const uint32_t stb = sb + st * STAGE_BYTES;
#pragma unroll
        for (int arr = 0; arr < 4; arr++) {
            const __nv_bfloat16* s = gsrc[arr] + kc * KC + lseg * 8;
            uint32_t d = stb + arr * ARR_BYTES + lrow * (RPAD * 2) + lseg * 16;
#pragma unroll
            for (int i = 0; i < 4; i++)
                CP_ASYNC16(d + i * 16, s + i * 8);
        }
        CP_COMMIT();
    };

    float acc[2][8][4];
#pragma unroll
    for (int mt = 0; mt < 2; mt++)
#pragma unroll
        for (int nt = 0; nt < 8; nt++)
#pragma unroll
            for (int r = 0; r < 4; r++) acc[mt][nt][r] = 0.f;

    issue_chunk(0);
    issue_chunk(1);

    // ldmatrix base offsets (within an array): row = (lane&15), col-half = lane>>4
    const uint32_t lm_row = (uint32_t)(lane & 15);
    const uint32_t lm_colb = (uint32_t)(lane >> 4) * 16;  // bytes

    for (int kc = 0; kc < 8; kc++) {
        const int st = kc & 1;
        const uint32_t stb = sb + st * STAGE_BYTES;
        CP_WAIT1();
        __syncthreads();

        const uint32_t Ahi = stb;
        const uint32_t Alo = stb + ARR_BYTES;
        const uint32_t Bhi = stb + 2 * ARR_BYTES;
        const uint32_t Blo = stb + 3 * ARR_BYTES;

#pragma unroll
        for (int kk = 0; kk < 4; kk++) {
            const uint32_t kb = lm_colb + kk * 32;  // byte offset along k

            uint32_t ah[2][4], al[2][4], bb[4][4];
#pragma unroll
            for (int mt = 0; mt < 2; mt++) {
                uint32_t aoff = (wg * 32 + mt * 16 + lm_row) * (RPAD * 2) + kb;
                LDMATRIX_X4(ah[mt][0], ah[mt][1], ah[mt][2], ah[mt][3], Ahi + aoff);
                LDMATRIX_X4(al[mt][0], al[mt][1], al[mt][2], al[mt][3], Alo + aoff);
            }
#pragma unroll
            for (int nt2 = 0; nt2 < 4; nt2++) {
                uint32_t boff = (wm * 64 + nt2 * 16 + lm_row) * (RPAD * 2) + kb;
                LDMATRIX_X4(bb[nt2][0], bb[nt2][1], bb[nt2][2], bb[nt2][3], Bhi + boff);
            }
            // Ah*Bh and Al*Bh
#pragma unroll
            for (int mt = 0; mt < 2; mt++)
#pragma unroll
                for (int nt = 0; nt < 8; nt++) {
                    uint32_t bfrag[2] = { bb[nt >> 1][nt & 1], bb[nt >> 1][(nt & 1) + 2] };
                    MMA_BF16(acc[mt][nt], ah[mt], bfrag);
                    MMA_BF16(acc[mt][nt], al[mt], bfrag);
                }
            // Bl pass: Ah*Bl
#pragma unroll
            for (int nt2 = 0; nt2 < 4; nt2++) {
                uint32_t boff = (wm * 64 + nt2 * 16 + lm_row) * (RPAD * 2) + kb;
                LDMATRIX_X4(bb[nt2][0], bb[nt2][1], bb[nt2][2], bb[nt2][3], Blo + boff);
            }
#pragma unroll
            for (int mt = 0; mt < 2; mt++)
#pragma unroll
                for (int nt = 0; nt < 8; nt++) {
                    uint32_t bfrag[2] = { bb[nt >> 1][nt & 1], bb[nt >> 1][(nt & 1) + 2] };
                    MMA_BF16(acc[mt][nt], ah[mt], bfrag);
                }
        }
        __syncthreads();
        if (kc + 2 < 8) issue_chunk(kc + 2);
    }

    // Epilogue: transposed scatter with fused bias.
    // lane element (mt, half, nt, pair): g = g0+wg*32+mt*16+half*8+grp,
    //                                    m = m0+wm*64+nt*8+2*tig (+pair)
    float bias[2][2];
    float* rowp[2][2];
#pragma unroll
    for (int mt = 0; mt < 2; mt++)
#pragma unroll
        for (int hf = 0; hf < 2; hf++) {
            int g = g0 + wg * 32 + mt * 16 + hf * 8 + grp;
            bias[mt][hf] = bih[g] + bhh[g];
            int d = g >> 11, gp = g & 2047;
            rowp[mt][hf] = g_xpre + ((size_t)d * T_LEN) * (G4 * BATCH) + (size_t)gp * BATCH;
        }
#pragma unroll
    for (int mt = 0; mt < 2; mt++)
#pragma unroll
        for (int nt = 0; nt < 8; nt++) {
            int m = m0 + wm * 64 + nt * 8 + 2 * tig;
            int t = m >> 5, b = m & 31;
            size_t toff = (size_t)t * (G4 * BATCH) + b;
            float2 v0 = { acc[mt][nt][0] + bias[mt][0], acc[mt][nt][1] + bias[mt][0] };
            float2 v1 = { acc[mt][nt][2] + bias[mt][1], acc[mt][nt][3] + bias[mt][1] };
            *(float2*)(rowp[mt][0] + toff) = v0;
            *(float2*)(rowp[mt][1] + toff) = v1;
        }
}

// ---------------------------------------------------------------------------
// Phase 2: persistent recurrence kernel (unchanged, known-good).
// ---------------------------------------------------------------------------
#define HPAD 516

__global__ void lstm_rec_kernel(const float* __restrict__ h0,
                                const float* __restrict__ c0,
                                const float* __restrict__ Whh,
                                float* __restrict__ out,
                                float* __restrict__ hout,
                                float* __restrict__ cout)
{
    extern __shared__ float sm[];
    float* Wsh  = sm;
    float* hsh  = Wsh + 32 * HPAD;
    float* gbuf = hsh + 32 * HPAD;
    float* csl  = gbuf + 32 * 33;

    const int cta  = blockIdx.x;
    const int dir  = cta >> 6;
    const int j0   = (cta & (NCTA_DIR - 1)) * 8;
    const int tid  = threadIdx.x;
    const int warp = tid >> 5;
    const int lane = tid & 31;

    {
        int lr = tid >> 3, part = tid & 7;
        int q = lr >> 3, cc = lr & 7;
        const float* src = Whh + ((size_t)dir * G4 + q * DIM + j0 + cc) * DIM + part * 64;
        float* dst = Wsh + lr * HPAD + part * 64;
#pragma unroll
        for (int i = 0; i < 64; i += 4)
            *(float4*)(dst + i) = *(const float4*)(src + i);
    }
    {
        int cc = tid >> 5, b = tid & 31;
        csl[cc * 32 + b] = c0[((size_t)dir * BATCH + b) * DIM + j0 + cc];
    }
    __syncthreads();

    const float* w0 = Wsh + (warp * 4 + 0) * HPAD;
    const float* w1 = Wsh + (warp * 4 + 1) * HPAD;
    const float* w2 = Wsh + (warp * 4 + 2) * HPAD;
    const float* w3 = Wsh + (warp * 4 + 3) * HPAD;
    const float* hrow = hsh + lane * HPAD;

    for (int s = 0; s < T_LEN; s++) {
        const int t = dir ? (T_LEN - 1 - s) : s;

        const float* hsrc;
        int hstride;
        if (s == 0) {
            hsrc = h0 + (size_t)dir * BATCH * DIM;
            hstride = DIM;
        } else {
            int tp = dir ? (t + 1) : (t - 1);
            hsrc = out + (size_t)tp * (BATCH * 1024) + dir * DIM;
            hstride = 1024;
            if (tid == 0) {
                volatile int* f = &g_sync[dir * T_LEN + (s - 1)];
                while (*f < NCTA_DIR) { __nanosleep(64); }
            }
            __syncthreads();
            __threadfence();
        }

#pragma unroll
        for (int it = 0; it < 16; it++) {
            int f  = tid + it * 256;
            int b  = f >> 7;
            int c4 = (f & 127) * 4;
            *(float4*)(hsh + b * HPAD + c4) =
                *(const float4*)(hsrc + (size_t)b * hstride + c4);
        }
        __syncthreads();

        float a0 = 0.f, a1 = 0.f, a2 = 0.f, a3 = 0.f;
#pragma unroll 8
        for (int k4 = 0; k4 < DIM / 4; k4++) {
            float4 hv = *(const float4*)(hrow + k4 * 4);
            float4 wv;
            wv = *(const float4*)(w0 + k4 * 4);
            a0 += wv.x * hv.x + wv.y * hv.y + wv.z * hv.z + wv.w * hv.w;
            wv = *(const float4*)(w1 + k4 * 4);
            a1 += wv.x * hv.x + wv.y * hv.y + wv.z * hv.z + wv.w * hv.w;
            wv = *(const float4*)(w2 + k4 * 4);
            a2 += wv.x * hv.x + wv.y * hv.y + wv.z * hv.z + wv.w * hv.w;
            wv = *(const float4*)(w3 + k4 * 4);
            a3 += wv.x * hv.x + wv.y * hv.y + wv.z * hv.z + wv.w * hv.w;
        }

        {
            const float* xp = g_xpre + (size_t)dir * ((size_t)T_LEN * G4 * BATCH)
                                     + (size_t)t * (G4 * BATCH);
            float av[4] = {a0, a1, a2, a3};
#pragma unroll
            for (int r = 0; r < 4; r++) {
                int lr = warp * 4 + r;
                int g  = (lr >> 3) * DIM + j0 + (lr & 7);
                gbuf[lr * 33 + lane] = av[r] + xp[(size_t)g * BATCH + lane];
            }
        }
        __syncthreads();

        {
            int cc = tid >> 5, b = tid & 31;
            float xi = gbuf[(0  + cc) * 33 + b];
            float xf = gbuf[(8  + cc) * 33 + b];
            float xg = gbuf[(16 + cc) * 33 + b];
            float xo = gbuf[(24 + cc) * 33 + b];
            float ig = 1.f / (1.f + __expf(-xi));
            float fg = 1.f / (1.f + __expf(-xf));
            float gg = tanhf(xg);
            float og = 1.f / (1.f + __expf(-xo));
            float c  = fg * csl[cc * 32 + b] + ig * gg;
            csl[cc * 32 + b] = c;
            float h  = og * tanhf(c);
            out[(size_t)t * (BATCH * 1024) + (size_t)b * 1024 + dir * DIM + j0 + cc] = h;
            if (s == T_LEN - 1) {
                hout[((size_t)dir * BATCH + b) * DIM + j0 + cc] = h;
                cout[((size_t)dir * BATCH + b) * DIM + j0 + cc] = c;
            }
        }

        __threadfence();
        __syncthreads();
        if (tid == 0) atomicAdd(&g_sync[dir * T_LEN + s], 1);
    }
}

// ---------------------------------------------------------------------------
// launch
// ---------------------------------------------------------------------------
extern "C" void kernel_launch(void* const* d_in, const int* in_sizes, int n_in,
                              void* d_out, int out_size)
{
    (void)in_sizes; (void)n_in; (void)out_size;
    const float* x   = (const float*)d_in[0];
    const float* h0  = (const float*)d_in[1];
    const float* c0  = (const float*)d_in[2];
    const float* Wih = (const float*)d_in[3];
    const float* bih = (const float*)d_in[4];
    const float* Whh = (const float*)d_in[5];
    const float* bhh = (const float*)d_in[6];

    float* out  = (float*)d_out;
    float* hout = out + (size_t)T_LEN * BATCH * 1024;
    float* cout = hout + (size_t)2 * BATCH * DIM;

    init_sync_kernel<<<4, 256>>>();

    __nv_bfloat16 *xhi, *xlo, *whi, *wlo;
    cudaGetSymbolAddress((void**)&xhi, g_xhi);
    cudaGetSymbolAddress((void**)&xlo, g_xlo);
    cudaGetSymbolAddress((void**)&whi, g_whi);
    cudaGetSymbolAddress((void**)&wlo, g_wlo);
    {
        int nx = 16384 * 512;
        split_kernel<<<nx / 4 / 256, 256>>>(x, xhi, xlo, nx);
        int nw = 4096 * 512;
        split_kernel<<<nw / 4 / 256, 256>>>(Wih, whi, wlo, nw);
    }

    {
        size_t smem = 2 * STAGE_BYTES;
        cudaFuncSetAttribute(xpre_mma_kernel,
                             cudaFuncAttributeMaxDynamicSharedMemorySize, (int)smem);
        dim3 grid(4096 / 128, 16384 / 128);
        xpre_mma_kernel<<<grid, 256, smem>>>(bih, bhh);
    }

    size_t smem2 = (size_t)(2 * 32 * HPAD + 32 * 33 + 8 * 32) * sizeof(float);
    cudaFuncSetAttribute(lstm_rec_kernel,
                         cudaFuncAttributeMaxDynamicSharedMemorySize, (int)smem2);
    lstm_rec_kernel<<<2 * NCTA_DIR, 256, smem2>>>(h0, c0, Whh, out, hout, cout);
}

// round 4
// speedup vs baseline: 1.8411x; 1.7441x over previous
#include <cuda_runtime.h>
#include <cuda_bf16.h>
#include <cstdint>

// Problem constants
#define T_LEN 512
#define BATCH 32
#define DIM   512   // D == H
#define G4    2048  // 4*H
#define NCTA_DIR 64 // recurrence CTAs per direction (8 H-cols each)

// Scratch
__device__ float g_xpre[(size_t)2 * T_LEN * G4 * BATCH]; // [dir][t][g][b]
__device__ int   g_sync[2 * T_LEN];

// bf16 hi/lo split scratch for phase-1 GEMM
__device__ __nv_bfloat16 g_xhi[(size_t)16384 * 512];
__device__ __nv_bfloat16 g_xlo[(size_t)16384 * 512];
__device__ __nv_bfloat16 g_whi[(size_t)4096 * 512];
__device__ __nv_bfloat16 g_wlo[(size_t)4096 * 512];

// h history in split bf16: [dir][t][b][512]
__device__ __nv_bfloat16 g_hhi[(size_t)2 * T_LEN * BATCH * DIM];
__device__ __nv_bfloat16 g_hlo[(size_t)2 * T_LEN * BATCH * DIM];

__device__ __forceinline__ uint32_t smem_to_u32(const void* p) {
    uint32_t a;
    asm("{ .reg .u64 t; cvta.to.shared.u64 t, %1; cvt.u32.u64 %0, t; }" : "=r"(a) : "l"(p));
    return a;
}

#define CP_ASYNC16(dst, src) \
    asm volatile("cp.async.cg.shared.global [%0], [%1], 16;" :: "r"(dst), "l"(src) : "memory")
#define CP_COMMIT() asm volatile("cp.async.commit_group;" ::: "memory")
#define CP_WAIT1()  asm volatile("cp.async.wait_group 1;" ::: "memory")
#define CP_WAIT0()  asm volatile("cp.async.wait_group 0;" ::: "memory")

#define LDMATRIX_X4(r0, r1, r2, r3, addr) \
    asm volatile("ldmatrix.sync.aligned.m8n8.x4.shared.b16 {%0,%1,%2,%3}, [%4];" \
        : "=r"(r0), "=r"(r1), "=r"(r2), "=r"(r3) : "r"(addr))
#define LDMATRIX_X2(r0, r1, addr) \
    asm volatile("ldmatrix.sync.aligned.m8n8.x2.shared.b16 {%0,%1}, [%2];" \
        : "=r"(r0), "=r"(r1) : "r"(addr))

#define MMA_BF16(d, a, b) \
    asm volatile("mma.sync.aligned.m16n8k16.row.col.f32.bf16.bf16.f32 " \
        "{%0,%1,%2,%3}, {%4,%5,%6,%7}, {%8,%9}, {%0,%1,%2,%3};" \
        : "+f"((d)[0]), "+f"((d)[1]), "+f"((d)[2]), "+f"((d)[3]) \
        : "r"((a)[0]), "r"((a)[1]), "r"((a)[2]), "r"((a)[3]), "r"((b)[0]), "r"((b)[1]))

// pack two fp32 into bf16x2 (lo = a, hi = b)
__device__ __forceinline__ uint32_t pack_bf16(float a, float b) {
    uint32_t r;
    asm("cvt.rn.bf16x2.f32 %0, %1, %2;" : "=r"(r) : "f"(b), "f"(a));
    return r;
}

// ---------------------------------------------------------------------------
__global__ void init_sync_kernel() {
    int i = blockIdx.x * blockDim.x + threadIdx.x;
    if (i < 2 * T_LEN) g_sync[i] = 0;
}

// fp32 -> bf16 hi/lo split (phase-1 inputs)
__global__ void split_kernel(const float* __restrict__ src,
                             __nv_bfloat16* __restrict__ hi,
                             __nv_bfloat16* __restrict__ lo, int n) {
    int i = (blockIdx.x * blockDim.x + threadIdx.x) * 4;
    if (i >= n) return;
    float4 v = *(const float4*)(src + i);
    float vs[4] = {v.x, v.y, v.z, v.w};
#pragma unroll
    for (int j = 0; j < 4; j++) {
        __nv_bfloat16 h = __float2bfloat16_rn(vs[j]);
        hi[i + j] = h;
        lo[i + j] = __float2bfloat16_rn(vs[j] - __bfloat162float(h));
    }
}

// ---------------------------------------------------------------------------
// Phase 1 (unchanged, known-good): HMMA split-bf16 GEMM for x_pre.
// ---------------------------------------------------------------------------
#define KC 64
#define RPAD 72
#define ARR_BYTES (128 * RPAD * 2)
#define STAGE_BYTES (4 * ARR_BYTES)

__global__ __launch_bounds__(256, 1)
void xpre_mma_kernel(const float* __restrict__ bih, const float* __restrict__ bhh)
{
    extern __shared__ char smem[];
    const uint32_t sb = smem_to_u32(smem);

    const int tid  = threadIdx.x;
    const int wid  = tid >> 5;
    const int lane = tid & 31;
    const int g0   = blockIdx.x * 128;
    const int m0   = blockIdx.y * 128;
    const int wg   = wid >> 1;
    const int wm   = wid & 1;

    const int grp = lane >> 2;
    const int tig = lane & 3;

    const int lrow = tid >> 1;
    const int lseg = (tid & 1) * 4;
    const __nv_bfloat16* gsrc[4] = {
        g_whi + (size_t)(g0 + lrow) * 512,
        g_wlo + (size_t)(g0 + lrow) * 512,
        g_xhi + (size_t)(m0 + lrow) * 512,
        g_xlo + (size_t)(m0 + lrow) * 512
    };

    auto issue_chunk = [&](int kc) {
        const int st = kc & 1;
        const uint32_t stb = sb + st * STAGE_BYTES;
#pragma unroll
        for (int arr = 0; arr < 4; arr++) {
            const __nv_bfloat16* s = gsrc[arr] + kc * KC + lseg * 8;
            uint32_t d = stb + arr * ARR_BYTES + lrow * (RPAD * 2) + lseg * 16;
#pragma unroll
            for (int i = 0; i < 4; i++)
                CP_ASYNC16(d + i * 16, s + i * 8);
        }
        CP_COMMIT();
    };

    float acc[2][8][4];
#pragma unroll
    for (int mt = 0; mt < 2; mt++)
#pragma unroll
        for (int nt = 0; nt < 8; nt++)
#pragma unroll
            for (int r = 0; r < 4; r++) acc[mt][nt][r] = 0.f;

    issue_chunk(0);
    issue_chunk(1);

    const uint32_t lm_row = (uint32_t)(lane & 15);
    const uint32_t lm_colb = (uint32_t)(lane >> 4) * 16;

    for (int kc = 0; kc < 8; kc++) {
        const int st = kc & 1;
        const uint32_t stb = sb + st * STAGE_BYTES;
        CP_WAIT1();
        __syncthreads();

        const uint32_t Ahi = stb;
        const uint32_t Alo = stb + ARR_BYTES;
        const uint32_t Bhi = stb + 2 * ARR_BYTES;
        const uint32_t Blo = stb + 3 * ARR_BYTES;

#pragma unroll
        for (int kk = 0; kk < 4; kk++) {
            const uint32_t kb = lm_colb + kk * 32;

            uint32_t ah[2][4], al[2][4], bb[4][4];
#pragma unroll
            for (int mt = 0; mt < 2; mt++) {
                uint32_t aoff = (wg * 32 + mt * 16 + lm_row) * (RPAD * 2) + kb;
                LDMATRIX_X4(ah[mt][0], ah[mt][1], ah[mt][2], ah[mt][3], Ahi + aoff);
                LDMATRIX_X4(al[mt][0], al[mt][1], al[mt][2], al[mt][3], Alo + aoff);
            }
#pragma unroll
            for (int nt2 = 0; nt2 < 4; nt2++) {
                uint32_t boff = (wm * 64 + nt2 * 16 + lm_row) * (RPAD * 2) + kb;
                LDMATRIX_X4(bb[nt2][0], bb[nt2][1], bb[nt2][2], bb[nt2][3], Bhi + boff);
            }
#pragma unroll
            for (int mt = 0; mt < 2; mt++)
#pragma unroll
                for (int nt = 0; nt < 8; nt++) {
                    uint32_t bfrag[2] = { bb[nt >> 1][nt & 1], bb[nt >> 1][(nt & 1) + 2] };
                    MMA_BF16(acc[mt][nt], ah[mt], bfrag);
                    MMA_BF16(acc[mt][nt], al[mt], bfrag);
                }
#pragma unroll
            for (int nt2 = 0; nt2 < 4; nt2++) {
                uint32_t boff = (wm * 64 + nt2 * 16 + lm_row) * (RPAD * 2) + kb;
                LDMATRIX_X4(bb[nt2][0], bb[nt2][1], bb[nt2][2], bb[nt2][3], Blo + boff);
            }
#pragma unroll
            for (int mt = 0; mt < 2; mt++)
#pragma unroll
                for (int nt = 0; nt < 8; nt++) {
                    uint32_t bfrag[2] = { bb[nt >> 1][nt & 1], bb[nt >> 1][(nt & 1) + 2] };
                    MMA_BF16(acc[mt][nt], ah[mt], bfrag);
                }
        }
        __syncthreads();
        if (kc + 2 < 8) issue_chunk(kc + 2);
    }

    float bias[2][2];
    float* rowp[2][2];
#pragma unroll
    for (int mt = 0; mt < 2; mt++)
#pragma unroll
        for (int hf = 0; hf < 2; hf++) {
            int g = g0 + wg * 32 + mt * 16 + hf * 8 + grp;
            bias[mt][hf] = bih[g] + bhh[g];
            int d = g >> 11, gp = g & 2047;
            rowp[mt][hf] = g_xpre + ((size_t)d * T_LEN) * (G4 * BATCH) + (size_t)gp * BATCH;
        }
#pragma unroll
    for (int mt = 0; mt < 2; mt++)
#pragma unroll
        for (int nt = 0; nt < 8; nt++) {
            int m = m0 + wm * 64 + nt * 8 + 2 * tig;
            int t = m >> 5, b = m & 31;
            size_t toff = (size_t)t * (G4 * BATCH) + b;
            float2 v0 = { acc[mt][nt][0] + bias[mt][0], acc[mt][nt][1] + bias[mt][0] };
            float2 v1 = { acc[mt][nt][2] + bias[mt][1], acc[mt][nt][3] + bias[mt][1] };
            *(float2*)(rowp[mt][0] + toff) = v0;
            *(float2*)(rowp[mt][1] + toff) = v1;
        }
}

// ---------------------------------------------------------------------------
// Phase 2 v2: persistent recurrence with split-bf16 mma.sync.
//   CTA = (dir, 8 H-cols). W_hh slice hi/lo in SMEM; B fragments preloaded
//   into registers (step-invariant). Per step: prefetch x_pre (cp.async) ->
//   flag wait -> cp.async h hi/lo -> MMA (3-pass) -> gbuf scatter ->
//   LSTM update -> write out fp32 + h hi/lo history -> release.
// ---------------------------------------------------------------------------
#define KPAD 520                       // bf16 elems per padded smem row (1040B)
#define WHI_OFF 0
#define WLO_OFF (32 * KPAD * 2)        // 33280
#define HHI_OFF (2 * 32 * KPAD * 2)    // 66560
#define HLO_OFF (3 * 32 * KPAD * 2)    // 99840
#define GB_OFF  (4 * 32 * KPAD * 2)    // 133120
#define XPS_OFF (GB_OFF + 32 * 33 * 4) // 137344
#define CSL_OFF (XPS_OFF + 32 * 36 * 4)// 141952
#define SMEM2_TOTAL (CSL_OFF + 8 * 32 * 4)

__global__ __launch_bounds__(256, 1)
void lstm_rec_mma_kernel(const float* __restrict__ h0,
                         const float* __restrict__ c0,
                         const float* __restrict__ Whh,
                         float* __restrict__ out,
                         float* __restrict__ hout,
                         float* __restrict__ cout)
{
    extern __shared__ char smraw[];
    const uint32_t sb = smem_to_u32(smraw);
    float* gbuf = (float*)(smraw + GB_OFF);
    float* xps  = (float*)(smraw + XPS_OFF);
    float* csl  = (float*)(smraw + CSL_OFF);
    uint32_t* Whi32 = (uint32_t*)(smraw + WHI_OFF);
    uint32_t* Wlo32 = (uint32_t*)(smraw + WLO_OFF);
    uint32_t* Hhi32 = (uint32_t*)(smraw + HHI_OFF);
    uint32_t* Hlo32 = (uint32_t*)(smraw + HLO_OFF);

    const int cta  = blockIdx.x;
    const int dir  = cta >> 6;
    const int j0   = (cta & (NCTA_DIR - 1)) * 8;
    const int tid  = threadIdx.x;
    const int wid  = tid >> 5;
    const int lane = tid & 31;
    const int m0w  = (wid >> 2) * 16;   // batch tile base
    const int n0w  = (wid & 3) * 8;     // gate-row tile base

    // ---- load & split W_hh slice into smem bf16 hi/lo ----
    {
        int lr = tid >> 3, seg = tid & 7;
        int gr = (lr >> 3) * DIM + j0 + (lr & 7);
        const float4* src = (const float4*)(Whh + ((size_t)dir * G4 + gr) * DIM + seg * 64);
#pragma unroll
        for (int i = 0; i < 16; i++) {
            float4 v = src[i];
            int k = seg * 64 + i * 4;
            float h0f = __bfloat162float(__float2bfloat16_rn(v.x));
            float h1f = __bfloat162float(__float2bfloat16_rn(v.y));
            float h2f = __bfloat162float(__float2bfloat16_rn(v.z));
            float h3f = __bfloat162float(__float2bfloat16_rn(v.w));
            int u = (lr * KPAD + k) >> 1;
            Whi32[u]     = pack_bf16(h0f, h1f);
            Whi32[u + 1] = pack_bf16(h2f, h3f);
            Wlo32[u]     = pack_bf16(v.x - h0f, v.y - h1f);
            Wlo32[u + 1] = pack_bf16(v.z - h2f, v.w - h3f);
        }
    }
    // c state slice
    {
        int cc = tid >> 5, b = tid & 31;
        csl[cc * 32 + b] = c0[((size_t)dir * BATCH + b) * DIM + j0 + cc];
    }
    __syncthreads();

    // ---- preload B (W) fragments into registers: step-invariant ----
    uint32_t bh[32][2], bl[32][2];
    {
        uint32_t brow = (uint32_t)(n0w + (lane & 7));
        uint32_t bcol = (uint32_t)((lane >> 3) & 1) * 16;
        uint32_t bhb = sb + WHI_OFF + brow * (KPAD * 2) + bcol;
        uint32_t blb = sb + WLO_OFF + brow * (KPAD * 2) + bcol;
#pragma unroll
        for (int ks = 0; ks < 32; ks++) {
            LDMATRIX_X2(bh[ks][0], bh[ks][1], bhb + ks * 32);
            LDMATRIX_X2(bl[ks][0], bl[ks][1], blb + ks * 32);
        }
    }

    const uint32_t arow = (uint32_t)(m0w + (lane & 15));
    const uint32_t acol = (uint32_t)(lane >> 4) * 16;
    const uint32_t ahb = sb + HHI_OFF + arow * (KPAD * 2) + acol;
    const uint32_t alb = sb + HLO_OFF + arow * (KPAD * 2) + acol;

    const int cc_u = tid >> 5;       // update-phase row
    const int b_u  = tid & 31;

    for (int s = 0; s < T_LEN; s++) {
        const int t = dir ? (T_LEN - 1 - s) : s;

        // prefetch x_pre slice (independent of h) BEFORE the flag wait
        {
            int lr = tid >> 3, seg = tid & 7;
            int gp = (lr >> 3) * DIM + j0 + (lr & 7);
            const float* src = g_xpre + (size_t)dir * ((size_t)T_LEN * G4 * BATCH)
                             + (size_t)t * (G4 * BATCH) + (size_t)gp * BATCH + seg * 4;
            CP_ASYNC16(sb + XPS_OFF + (uint32_t)(lr * 144 + seg * 16), src);
            CP_COMMIT();
        }

        if (s == 0) {
            // convert h0 fp32 -> smem bf16 hi/lo
            const float4* h0p = (const float4*)(h0 + (size_t)dir * BATCH * DIM);
#pragma unroll
            for (int it = 0; it < 16; it++) {
                int idx = tid + it * 256;       // 0..4095 float4s
                int b = idx >> 7, c4 = (idx & 127) * 4;
                float4 v = h0p[idx];
                float f0 = __bfloat162float(__float2bfloat16_rn(v.x));
                float f1 = __bfloat162float(__float2bfloat16_rn(v.y));
                float f2 = __bfloat162float(__float2bfloat16_rn(v.z));
                float f3 = __bfloat162float(__float2bfloat16_rn(v.w));
                int u = (b * KPAD + c4) >> 1;
                Hhi32[u]     = pack_bf16(f0, f1);
                Hhi32[u + 1] = pack_bf16(f2, f3);
                Hlo32[u]     = pack_bf16(v.x - f0, v.y - f1);
                Hlo32[u + 1] = pack_bf16(v.z - f2, v.w - f3);
            }
            CP_WAIT0();
            __syncthreads();
        } else {
            if (tid == 0) {
                volatile int* f = &g_sync[dir * T_LEN + (s - 1)];
                while (*f < NCTA_DIR) { }
                __threadfence();
            }
            __syncthreads();
            // cp.async h hi/lo [32][512] bf16
            const int tp = dir ? (t + 1) : (t - 1);
            const __nv_bfloat16* hh = g_hhi + (size_t)(dir * T_LEN + tp) * (BATCH * DIM);
            const __nv_bfloat16* hl = g_hlo + (size_t)(dir * T_LEN + tp) * (BATCH * DIM);
#pragma unroll
            for (int i = 0; i < 8; i++) {
                int lin = tid + i * 256;
                int b = lin >> 6, sg = lin & 63;
                uint32_t doff = (uint32_t)(b * KPAD + sg * 8) * 2;
                CP_ASYNC16(sb + HHI_OFF + doff, hh + (size_t)b * DIM + sg * 8);
                CP_ASYNC16(sb + HLO_OFF + doff, hl + (size_t)b * DIM + sg * 8);
            }
            CP_COMMIT();
            CP_WAIT0();
            __syncthreads();
        }

        // ---- MMA: acc = h @ W_slice^T (3-pass split-bf16) ----
        float acc[4] = {0.f, 0.f, 0.f, 0.f};
#pragma unroll
        for (int ks = 0; ks < 32; ks++) {
            uint32_t a_h[4], a_l[4];
            LDMATRIX_X4(a_h[0], a_h[1], a_h[2], a_h[3], ahb + ks * 32);
            LDMATRIX_X4(a_l[0], a_l[1], a_l[2], a_l[3], alb + ks * 32);
            MMA_BF16(acc, a_h, bh[ks]);
            MMA_BF16(acc, a_l, bh[ks]);
            MMA_BF16(acc, a_h, bl[ks]);
        }

        // scatter accumulators to gbuf[n][b]
        {
            int grp = lane >> 2, tig = lane & 3;
            int na = n0w + 2 * tig;
            int b1 = m0w + grp, b2 = b1 + 8;
            gbuf[na * 33 + b1]       = acc[0];
            gbuf[(na + 1) * 33 + b1] = acc[1];
            gbuf[na * 33 + b2]       = acc[2];
            gbuf[(na + 1) * 33 + b2] = acc[3];
        }
        __syncthreads();

        // ---- LSTM elementwise update: thread -> (cc_u, b_u) ----
        {
            float xi = gbuf[cc_u * 33 + b_u]        + xps[cc_u * 36 + b_u];
            float xf = gbuf[(8 + cc_u) * 33 + b_u]  + xps[(8 + cc_u) * 36 + b_u];
            float xg = gbuf[(16 + cc_u) * 33 + b_u] + xps[(16 + cc_u) * 36 + b_u];
            float xo = gbuf[(24 + cc_u) * 33 + b_u] + xps[(24 + cc_u) * 36 + b_u];
            float ig = 1.f / (1.f + __expf(-xi));
            float fg = 1.f / (1.f + __expf(-xf));
            float gg = tanhf(xg);
            float og = 1.f / (1.f + __expf(-xo));
            float c  = fg * csl[cc_u * 32 + b_u] + ig * gg;
            csl[cc_u * 32 + b_u] = c;
            float h  = og * tanhf(c);

            out[(size_t)t * (BATCH * 1024) + (size_t)b_u * 1024 + dir * DIM + j0 + cc_u] = h;

            // split h -> bf16 history
            __nv_bfloat16 hh = __float2bfloat16_rn(h);
            __nv_bfloat16 hl = __float2bfloat16_rn(h - __bfloat162float(hh));
            size_t hoff = (size_t)(dir * T_LEN + t) * (BATCH * DIM) + (size_t)b_u * DIM + j0 + cc_u;
            g_hhi[hoff] = hh;
            g_hlo[hoff] = hl;

            if (s == T_LEN - 1) {
                hout[((size_t)dir * BATCH + b_u) * DIM + j0 + cc_u] = h;
                cout[((size_t)dir * BATCH + b_u) * DIM + j0 + cc_u] = c;
            }
        }

        __syncthreads();
        if (tid == 0) {
            __threadfence();
            atomicAdd(&g_sync[dir * T_LEN + s], 1);
        }
    }
}

// ---------------------------------------------------------------------------
// launch
// ---------------------------------------------------------------------------
extern "C" void kernel_launch(void* const* d_in, const int* in_sizes, int n_in,
                              void* d_out, int out_size)
{
    (void)in_sizes; (void)n_in; (void)out_size;
    const float* x   = (const float*)d_in[0];
    const float* h0  = (const float*)d_in[1];
    const float* c0  = (const float*)d_in[2];
    const float* Wih = (const float*)d_in[3];
    const float* bih = (const float*)d_in[4];
    const float* Whh = (const float*)d_in[5];
    const float* bhh = (const float*)d_in[6];

    float* out  = (float*)d_out;
    float* hout = out + (size_t)T_LEN * BATCH * 1024;
    float* cout = hout + (size_t)2 * BATCH * DIM;

    init_sync_kernel<<<4, 256>>>();

    __nv_bfloat16 *xhi, *xlo, *whi, *wlo;
    cudaGetSymbolAddress((void**)&xhi, g_xhi);
    cudaGetSymbolAddress((void**)&xlo, g_xlo);
    cudaGetSymbolAddress((void**)&whi, g_whi);
    cudaGetSymbolAddress((void**)&wlo, g_wlo);
    {
        int nx = 16384 * 512;
        split_kernel<<<nx / 4 / 256, 256>>>(x, xhi, xlo, nx);
        int nw = 4096 * 512;
        split_kernel<<<nw / 4 / 256, 256>>>(Wih, whi, wlo, nw);
    }

    {
        size_t smem = 2 * STAGE_BYTES;
        cudaFuncSetAttribute(xpre_mma_kernel,
                             cudaFuncAttributeMaxDynamicSharedMemorySize, (int)smem);
        dim3 grid(4096 / 128, 16384 / 128);
        xpre_mma_kernel<<<grid, 256, smem>>>(bih, bhh);
    }

    {
        cudaFuncSetAttribute(lstm_rec_mma_kernel,
                             cudaFuncAttributeMaxDynamicSharedMemorySize, SMEM2_TOTAL);
        lstm_rec_mma_kernel<<<2 * NCTA_DIR, 256, SMEM2_TOTAL>>>(h0, c0, Whh, out, hout, cout);
    }
}

// round 5
// speedup vs baseline: 2.0482x; 1.1125x over previous
#include <cuda_runtime.h>
#include <cuda_bf16.h>
#include <cstdint>

// Problem constants
#define T_LEN 512
#define BATCH 32
#define DIM   512   // D == H
#define G4    2048  // 4*H
#define NCTA_DIR 64 // recurrence CTAs per direction (8 H-cols each)

// Scratch
__device__ float g_xpre[(size_t)2 * T_LEN * G4 * BATCH]; // [dir][t][g][b]
__device__ int   g_sync[2 * T_LEN];

// bf16 hi/lo split scratch for phase-1 GEMM
__device__ __nv_bfloat16 g_xhi[(size_t)16384 * 512];
__device__ __nv_bfloat16 g_xlo[(size_t)16384 * 512];
__device__ __nv_bfloat16 g_whi[(size_t)4096 * 512];
__device__ __nv_bfloat16 g_wlo[(size_t)4096 * 512];

// h history in split bf16: [dir][t][b][512]
__device__ __nv_bfloat16 g_hhi[(size_t)2 * T_LEN * BATCH * DIM];
__device__ __nv_bfloat16 g_hlo[(size_t)2 * T_LEN * BATCH * DIM];

__device__ __forceinline__ uint32_t smem_to_u32(const void* p) {
    uint32_t a;
    asm("{ .reg .u64 t; cvta.to.shared.u64 t, %1; cvt.u32.u64 %0, t; }" : "=r"(a) : "l"(p));
    return a;
}

#define CP_ASYNC16(dst, src) \
    asm volatile("cp.async.cg.shared.global [%0], [%1], 16;" :: "r"(dst), "l"(src) : "memory")
#define CP_COMMIT() asm volatile("cp.async.commit_group;" ::: "memory")
#define CP_WAIT2()  asm volatile("cp.async.wait_group 2;" ::: "memory")
#define CP_WAIT0()  asm volatile("cp.async.wait_group 0;" ::: "memory")

#define LDMATRIX_X4(r0, r1, r2, r3, addr) \
    asm volatile("ldmatrix.sync.aligned.m8n8.x4.shared.b16 {%0,%1,%2,%3}, [%4];" \
        : "=r"(r0), "=r"(r1), "=r"(r2), "=r"(r3) : "r"(addr))
#define LDMATRIX_X2(r0, r1, addr) \
    asm volatile("ldmatrix.sync.aligned.m8n8.x2.shared.b16 {%0,%1}, [%2];" \
        : "=r"(r0), "=r"(r1) : "r"(addr))

#define MMA_BF16(d, a, b) \
    asm volatile("mma.sync.aligned.m16n8k16.row.col.f32.bf16.bf16.f32 " \
        "{%0,%1,%2,%3}, {%4,%5,%6,%7}, {%8,%9}, {%0,%1,%2,%3};" \
        : "+f"((d)[0]), "+f"((d)[1]), "+f"((d)[2]), "+f"((d)[3]) \
        : "r"((a)[0]), "r"((a)[1]), "r"((a)[2]), "r"((a)[3]), "r"((b)[0]), "r"((b)[1]))

__device__ __forceinline__ uint32_t pack_bf16(float a, float b) {
    uint32_t r;
    asm("cvt.rn.bf16x2.f32 %0, %1, %2;" : "=r"(r) : "f"(b), "f"(a));
    return r;
}

// ---------------------------------------------------------------------------
__global__ void init_sync_kernel() {
    int i = blockIdx.x * blockDim.x + threadIdx.x;
    if (i < 2 * T_LEN) g_sync[i] = 0;
}

__global__ void split_kernel(const float* __restrict__ src,
                             __nv_bfloat16* __restrict__ hi,
                             __nv_bfloat16* __restrict__ lo, int n) {
    int i = (blockIdx.x * blockDim.x + threadIdx.x) * 4;
    if (i >= n) return;
    float4 v = *(const float4*)(src + i);
    float vs[4] = {v.x, v.y, v.z, v.w};
#pragma unroll
    for (int j = 0; j < 4; j++) {
        __nv_bfloat16 h = __float2bfloat16_rn(vs[j]);
        hi[i + j] = h;
        lo[i + j] = __float2bfloat16_rn(vs[j] - __bfloat162float(h));
    }
}

// ---------------------------------------------------------------------------
// Phase 1: HMMA split-bf16 GEMM for x_pre. KC=32, 4 stages (3 in flight).
// ---------------------------------------------------------------------------
#define KC1 32
#define RPAD1 40                       // bf16 per padded row (80B)
#define ARR1 (128 * RPAD1 * 2)         // 10240
#define STAGE1 (4 * ARR1)              // 40960
#define NCHUNK1 16

__global__ __launch_bounds__(256, 1)
void xpre_mma_kernel(const float* __restrict__ bih, const float* __restrict__ bhh)
{
    extern __shared__ char smem[];
    const uint32_t sb = smem_to_u32(smem);

    const int tid  = threadIdx.x;
    const int wid  = tid >> 5;
    const int lane = tid & 31;
    const int g0   = blockIdx.x * 128;
    const int m0   = blockIdx.y * 128;
    const int wg   = wid >> 1;
    const int wm   = wid & 1;

    const int grp = lane >> 2;
    const int tig = lane & 3;

    const int lrow = tid >> 1;
    const __nv_bfloat16* gsrc[4] = {
        g_whi + (size_t)(g0 + lrow) * 512,
        g_wlo + (size_t)(g0 + lrow) * 512,
        g_xhi + (size_t)(m0 + lrow) * 512,
        g_xlo + (size_t)(m0 + lrow) * 512
    };

    auto issue_chunk = [&](int kc) {
        const uint32_t stb = sb + (kc & 3) * STAGE1;
#pragma unroll
        for (int arr = 0; arr < 4; arr++) {
#pragma unroll
            for (int i = 0; i < 2; i++) {
                int seg = (tid & 1) * 2 + i;
                CP_ASYNC16(stb + arr * ARR1 + lrow * (RPAD1 * 2) + seg * 16,
                           gsrc[arr] + kc * KC1 + seg * 8);
            }
        }
        CP_COMMIT();
    };

    float acc[2][8][4];
#pragma unroll
    for (int mt = 0; mt < 2; mt++)
#pragma unroll
        for (int nt = 0; nt < 8; nt++)
#pragma unroll
            for (int r = 0; r < 4; r++) acc[mt][nt][r] = 0.f;

    issue_chunk(0);
    issue_chunk(1);
    issue_chunk(2);

    const uint32_t lm_row = (uint32_t)(lane & 15);
    const uint32_t lm_colb = (uint32_t)(lane >> 4) * 16;

    for (int kc = 0; kc < NCHUNK1; kc++) {
        const uint32_t stb = sb + (kc & 3) * STAGE1;
        CP_WAIT2();
        __syncthreads();

        const uint32_t Ahi = stb;
        const uint32_t Alo = stb + ARR1;
        const uint32_t Bhi = stb + 2 * ARR1;
        const uint32_t Blo = stb + 3 * ARR1;

#pragma unroll
        for (int kk = 0; kk < 2; kk++) {
            const uint32_t kb = lm_colb + kk * 32;

            uint32_t ah[2][4], al[2][4], bb[4][4];
#pragma unroll
            for (int mt = 0; mt < 2; mt++) {
                uint32_t aoff = (wg * 32 + mt * 16 + lm_row) * (RPAD1 * 2) + kb;
                LDMATRIX_X4(ah[mt][0], ah[mt][1], ah[mt][2], ah[mt][3], Ahi + aoff);
                LDMATRIX_X4(al[mt][0], al[mt][1], al[mt][2], al[mt][3], Alo + aoff);
            }
#pragma unroll
            for (int nt2 = 0; nt2 < 4; nt2++) {
                uint32_t boff = (wm * 64 + nt2 * 16 + lm_row) * (RPAD1 * 2) + kb;
                LDMATRIX_X4(bb[nt2][0], bb[nt2][1], bb[nt2][2], bb[nt2][3], Bhi + boff);
            }
#pragma unroll
            for (int mt = 0; mt < 2; mt++)
#pragma unroll
                for (int nt = 0; nt < 8; nt++) {
                    uint32_t bfrag[2] = { bb[nt >> 1][nt & 1], bb[nt >> 1][(nt & 1) + 2] };
                    MMA_BF16(acc[mt][nt], ah[mt], bfrag);
                    MMA_BF16(acc[mt][nt], al[mt], bfrag);
                }
#pragma unroll
            for (int nt2 = 0; nt2 < 4; nt2++) {
                uint32_t boff = (wm * 64 + nt2 * 16 + lm_row) * (RPAD1 * 2) + kb;
                LDMATRIX_X4(bb[nt2][0], bb[nt2][1], bb[nt2][2], bb[nt2][3], Blo + boff);
            }
#pragma unroll
            for (int mt = 0; mt < 2; mt++)
#pragma unroll
                for (int nt = 0; nt < 8; nt++) {
                    uint32_t bfrag[2] = { bb[nt >> 1][nt & 1], bb[nt >> 1][(nt & 1) + 2] };
                    MMA_BF16(acc[mt][nt], ah[mt], bfrag);
                }
        }
        __syncthreads();
        if (kc + 3 < NCHUNK1) issue_chunk(kc + 3);
    }

    float bias[2][2];
    float* rowp[2][2];
#pragma unroll
    for (int mt = 0; mt < 2; mt++)
#pragma unroll
        for (int hf = 0; hf < 2; hf++) {
            int g = g0 + wg * 32 + mt * 16 + hf * 8 + grp;
            bias[mt][hf] = bih[g] + bhh[g];
            int d = g >> 11, gp = g & 2047;
            rowp[mt][hf] = g_xpre + ((size_t)d * T_LEN) * (G4 * BATCH) + (size_t)gp * BATCH;
        }
#pragma unroll
    for (int mt = 0; mt < 2; mt++)
#pragma unroll
        for (int nt = 0; nt < 8; nt++) {
            int m = m0 + wm * 64 + nt * 8 + 2 * tig;
            int t = m >> 5, b = m & 31;
            size_t toff = (size_t)t * (G4 * BATCH) + b;
            float2 v0 = { acc[mt][nt][0] + bias[mt][0], acc[mt][nt][1] + bias[mt][0] };
            float2 v1 = { acc[mt][nt][2] + bias[mt][1], acc[mt][nt][3] + bias[mt][1] };
            *(float2*)(rowp[mt][0] + toff) = v0;
            *(float2*)(rowp[mt][1] + toff) = v1;
        }
}

// ---------------------------------------------------------------------------
// Phase 2 v3: persistent recurrence, warp-local k-split.
//   Warp = (mhalf, kgroup): 16 batches x 32 gate rows x 128 k-slice.
//   Each warp cp.asyncs ITS OWN h sub-tile (no CTA barrier before MMA),
//   W fragments preloaded in regs, partials reduced via kgbuf.
// ---------------------------------------------------------------------------
#define KPAD 520
#define WHI_OFF 0
#define WLO_OFF (32 * KPAD * 2)            // 33280
#define HHI_OFF (2 * 32 * KPAD * 2)        // 66560
#define HLO_OFF (3 * 32 * KPAD * 2)        // 99840
#define KGB_OFF (4 * 32 * KPAD * 2)        // 133120
#define XPS_OFF (KGB_OFF + 4 * 32 * 33 * 4)// 150016
#define CSL_OFF (XPS_OFF + 32 * 36 * 4)    // 154624
#define SMEM2_TOTAL (CSL_OFF + 8 * 32 * 4)

__global__ __launch_bounds__(256, 1)
void lstm_rec_mma_kernel(const float* __restrict__ h0,
                         const float* __restrict__ c0,
                         const float* __restrict__ Whh,
                         float* __restrict__ out,
                         float* __restrict__ hout,
                         float* __restrict__ cout)
{
    extern __shared__ char smraw[];
    const uint32_t sb = smem_to_u32(smraw);
    float* kgb = (float*)(smraw + KGB_OFF);
    float* xps = (float*)(smraw + XPS_OFF);
    float* csl = (float*)(smraw + CSL_OFF);
    uint32_t* Whi32 = (uint32_t*)(smraw + WHI_OFF);
    uint32_t* Wlo32 = (uint32_t*)(smraw + WLO_OFF);
    uint32_t* Hhi32 = (uint32_t*)(smraw + HHI_OFF);
    uint32_t* Hlo32 = (uint32_t*)(smraw + HLO_OFF);

    const int cta  = blockIdx.x;
    const int dir  = cta >> 6;
    const int j0   = (cta & (NCTA_DIR - 1)) * 8;
    const int tid  = threadIdx.x;
    const int wid  = tid >> 5;
    const int lane = tid & 31;
    const int mhalf = wid >> 2;
    const int kg    = wid & 3;
    const int m0w   = mhalf * 16;

    // ---- load & split W_hh slice into smem bf16 hi/lo ----
    {
        int lr = tid >> 3, seg = tid & 7;
        int gr = (lr >> 3) * DIM + j0 + (lr & 7);
        const float4* src = (const float4*)(Whh + ((size_t)dir * G4 + gr) * DIM + seg * 64);
#pragma unroll
        for (int i = 0; i < 16; i++) {
            float4 v = src[i];
            int k = seg * 64 + i * 4;
            float f0 = __bfloat162float(__float2bfloat16_rn(v.x));
            float f1 = __bfloat162float(__float2bfloat16_rn(v.y));
            float f2 = __bfloat162float(__float2bfloat16_rn(v.z));
            float f3 = __bfloat162float(__float2bfloat16_rn(v.w));
            int u = (lr * KPAD + k) >> 1;
            Whi32[u]     = pack_bf16(f0, f1);
            Whi32[u + 1] = pack_bf16(f2, f3);
            Wlo32[u]     = pack_bf16(v.x - f0, v.y - f1);
            Wlo32[u + 1] = pack_bf16(v.z - f2, v.w - f3);
        }
    }
    {
        int cc = tid >> 5, b = tid & 31;
        csl[cc * 32 + b] = c0[((size_t)dir * BATCH + b) * DIM + j0 + cc];
    }
    __syncthreads();

    // ---- preload W fragments (step-invariant): bh/bl[nt][ks][2] ----
    uint32_t bh[4][8][2], bl[4][8][2];
    {
        const uint32_t brow = (uint32_t)(lane & 7);
        const uint32_t bcol = (uint32_t)((lane >> 3) & 1) * 16;
#pragma unroll
        for (int nt = 0; nt < 4; nt++)
#pragma unroll
            for (int ks = 0; ks < 8; ks++) {
                uint32_t off = (nt * 8 + brow) * (KPAD * 2) + kg * 256 + ks * 32 + bcol;
                LDMATRIX_X2(bh[nt][ks][0], bh[nt][ks][1], sb + WHI_OFF + off);
                LDMATRIX_X2(bl[nt][ks][0], bl[nt][ks][1], sb + WLO_OFF + off);
            }
    }

    const uint32_t arow_off = (uint32_t)(m0w + (lane & 15)) * (KPAD * 2)
                            + (uint32_t)kg * 256 + (uint32_t)(lane >> 4) * 16;

    const int cc_u = tid >> 5;
    const int b_u  = tid & 31;
    const int grp  = lane >> 2;
    const int tig  = lane & 3;

    for (int s = 0; s < T_LEN; s++) {
        const int t = dir ? (T_LEN - 1 - s) : s;

        // prefetch x_pre slice (independent of h) BEFORE the flag wait
        {
            int lr = tid >> 3, seg = tid & 7;
            int gp = (lr >> 3) * DIM + j0 + (lr & 7);
            const float* src = g_xpre + (size_t)dir * ((size_t)T_LEN * G4 * BATCH)
                             + (size_t)t * (G4 * BATCH) + (size_t)gp * BATCH + seg * 4;
            CP_ASYNC16(sb + XPS_OFF + (uint32_t)(lr * 144 + seg * 16), src);
            CP_COMMIT();
        }

        if (s == 0) {
            const float4* h0p = (const float4*)(h0 + (size_t)dir * BATCH * DIM);
#pragma unroll
            for (int it = 0; it < 16; it++) {
                int idx = tid + it * 256;
                int b = idx >> 7, c4 = (idx & 127) * 4;
                float4 v = h0p[idx];
                float f0 = __bfloat162float(__float2bfloat16_rn(v.x));
                float f1 = __bfloat162float(__float2bfloat16_rn(v.y));
                float f2 = __bfloat162float(__float2bfloat16_rn(v.z));
                float f3 = __bfloat162float(__float2bfloat16_rn(v.w));
                int u = (b * KPAD + c4) >> 1;
                Hhi32[u]     = pack_bf16(f0, f1);
                Hhi32[u + 1] = pack_bf16(f2, f3);
                Hlo32[u]     = pack_bf16(v.x - f0, v.y - f1);
                Hlo32[u + 1] = pack_bf16(v.z - f2, v.w - f3);
            }
            CP_WAIT0();
            __syncthreads();
        } else {
            if (tid == 0) {
                volatile int* f = &g_sync[dir * T_LEN + (s - 1)];
                while (*f < NCTA_DIR) { }
                __threadfence();
            }
            __syncthreads();
            // warp-local h cp.async: 16 batches x 128 k, hi+lo
            const int tp = dir ? (t + 1) : (t - 1);
            const __nv_bfloat16* hh = g_hhi + (size_t)(dir * T_LEN + tp) * (BATCH * DIM);
            const __nv_bfloat16* hl = g_hlo + (size_t)(dir * T_LEN + tp) * (BATCH * DIM);
#pragma unroll
            for (int it = 0; it < 8; it++) {
                int u = lane + it * 32;
                int r = u >> 4, sg = u & 15;
                int row = m0w + r;
                size_t goff = (size_t)row * DIM + kg * 128 + sg * 8;
                uint32_t doff = (uint32_t)(row * KPAD + kg * 128 + sg * 8) * 2;
                CP_ASYNC16(sb + HHI_OFF + doff, hh + goff);
                CP_ASYNC16(sb + HLO_OFF + doff, hl + goff);
            }
            CP_COMMIT();
            CP_WAIT0();   // per-warp: no CTA barrier before MMA
        }

        // ---- MMA: 16 batches x 32 gates, k-slice 128 (3-pass split-bf16) ----
        float acc[4][4];
#pragma unroll
        for (int nt = 0; nt < 4; nt++)
#pragma unroll
            for (int r = 0; r < 4; r++) acc[nt][r] = 0.f;

#pragma unroll
        for (int ks = 0; ks < 8; ks++) {
            uint32_t a_h[4], a_l[4];
            LDMATRIX_X4(a_h[0], a_h[1], a_h[2], a_h[3], sb + HHI_OFF + arow_off + ks * 32);
            LDMATRIX_X4(a_l[0], a_l[1], a_l[2], a_l[3], sb + HLO_OFF + arow_off + ks * 32);
#pragma unroll
            for (int nt = 0; nt < 4; nt++) {
                MMA_BF16(acc[nt], a_h, bh[nt][ks]);
                MMA_BF16(acc[nt], a_l, bh[nt][ks]);
                MMA_BF16(acc[nt], a_h, bl[nt][ks]);
            }
        }

        // scatter partials to kgb[kg][n][b]
        {
            float* kb = kgb + kg * (32 * 33);
            int b1 = m0w + grp, b2 = b1 + 8;
#pragma unroll
            for (int nt = 0; nt < 4; nt++) {
                int na = nt * 8 + 2 * tig;
                kb[na * 33 + b1]       = acc[nt][0];
                kb[(na + 1) * 33 + b1] = acc[nt][1];
                kb[na * 33 + b2]       = acc[nt][2];
                kb[(na + 1) * 33 + b2] = acc[nt][3];
            }
        }
        __syncthreads();

        // ---- LSTM update: thread -> (cc_u, b_u); reduce 4 k-partials ----
        {
            float xi = xps[cc_u * 36 + b_u];
            float xf = xps[(8 + cc_u) * 36 + b_u];
            float xg = xps[(16 + cc_u) * 36 + b_u];
            float xo = xps[(24 + cc_u) * 36 + b_u];
#pragma unroll
            for (int k = 0; k < 4; k++) {
                const float* kb = kgb + k * (32 * 33);
                xi += kb[cc_u * 33 + b_u];
                xf += kb[(8 + cc_u) * 33 + b_u];
                xg += kb[(16 + cc_u) * 33 + b_u];
                xo += kb[(24 + cc_u) * 33 + b_u];
            }
            float ig = 1.f / (1.f + __expf(-xi));
            float fg = 1.f / (1.f + __expf(-xf));
            float gg = tanhf(xg);
            float og = 1.f / (1.f + __expf(-xo));
            float c  = fg * csl[cc_u * 32 + b_u] + ig * gg;
            csl[cc_u * 32 + b_u] = c;
            float h  = og * tanhf(c);

            out[(size_t)t * (BATCH * 1024) + (size_t)b_u * 1024 + dir * DIM + j0 + cc_u] = h;

            __nv_bfloat16 hh = __float2bfloat16_rn(h);
            __nv_bfloat16 hl = __float2bfloat16_rn(h - __bfloat162float(hh));
            size_t hoff = (size_t)(dir * T_LEN + t) * (BATCH * DIM) + (size_t)b_u * DIM + j0 + cc_u;
            g_hhi[hoff] = hh;
            g_hlo[hoff] = hl;

            if (s == T_LEN - 1) {
                hout[((size_t)dir * BATCH + b_u) * DIM + j0 + cc_u] = h;
                cout[((size_t)dir * BATCH + b_u) * DIM + j0 + cc_u] = c;
            }
        }

        __syncthreads();
        if (tid == 0) {
            __threadfence();
            atomicAdd(&g_sync[dir * T_LEN + s], 1);
        }
    }
}

// ---------------------------------------------------------------------------
// launch
// ---------------------------------------------------------------------------
extern "C" void kernel_launch(void* const* d_in, const int* in_sizes, int n_in,
                              void* d_out, int out_size)
{
    (void)in_sizes; (void)n_in; (void)out_size;
    const float* x   = (const float*)d_in[0];
    const float* h0  = (const float*)d_in[1];
    const float* c0  = (const float*)d_in[2];
    const float* Wih = (const float*)d_in[3];
    const float* bih = (const float*)d_in[4];
    const float* Whh = (const float*)d_in[5];
    const float* bhh = (const float*)d_in[6];

    float* out  = (float*)d_out;
    float* hout = out + (size_t)T_LEN * BATCH * 1024;
    float* cout = hout + (size_t)2 * BATCH * DIM;

    init_sync_kernel<<<4, 256>>>();

    __nv_bfloat16 *xhi, *xlo, *whi, *wlo;
    cudaGetSymbolAddress((void**)&xhi, g_xhi);
    cudaGetSymbolAddress((void**)&xlo, g_xlo);
    cudaGetSymbolAddress((void**)&whi, g_whi);
    cudaGetSymbolAddress((void**)&wlo, g_wlo);
    {
        int nx = 16384 * 512;
        split_kernel<<<nx / 4 / 256, 256>>>(x, xhi, xlo, nx);
        int nw = 4096 * 512;
        split_kernel<<<nw / 4 / 256, 256>>>(Wih, whi, wlo, nw);
    }

    {
        size_t smem = 4 * STAGE1;
        cudaFuncSetAttribute(xpre_mma_kernel,
                             cudaFuncAttributeMaxDynamicSharedMemorySize, (int)smem);
        dim3 grid(4096 / 128, 16384 / 128);
        xpre_mma_kernel<<<grid, 256, smem>>>(bih, bhh);
    }

    {
        cudaFuncSetAttribute(lstm_rec_mma_kernel,
                             cudaFuncAttributeMaxDynamicSharedMemorySize, SMEM2_TOTAL);
        lstm_rec_mma_kernel<<<2 * NCTA_DIR, 256, SMEM2_TOTAL>>>(h0, c0, Whh, out, hout, cout);
    }
}